// round 17
// baseline (speedup 1.0000x reference)
#include <cuda_runtime.h>
#include <cstdint>

__device__ __forceinline__ void cp_async16(void* smem_dst, const void* gmem_src) {
    uint32_t s = (uint32_t)__cvta_generic_to_shared(smem_dst);
    asm volatile("cp.async.cg.shared.global [%0], [%1], 16;"
                 :: "r"(s), "l"(gmem_src));
}

// ---------------------------------------------------------------------------
// Fully fused kernel: MLP (gemm1 + leakyrelu + gemm2 + softmaxes) + expansion.
// grid 128, block 640, 4 rows per block: rows B, B+128, B+256, B+384
// (all share pad = B & 3 since 128 % 4 == 0).
//
// Dynamic smem carve (floats):
//   tile[2][256][36]  w2 double buffer     [0, 18432)
//   xs[4][512]        x rows               [18432, 20480)
//   sv[4][1284]       run values           [20480, 25616)
//   hs[4][260]        hidden rows          [25616, 26656)
//   ps[4][64]         probability rows     [26656, 26912)
//   zs[4][60]         logits               [26912, 27152)
// Total 27152 floats = 108,608 bytes.
// ---------------------------------------------------------------------------
__global__ void __launch_bounds__(640) fused_kernel(
    const float* __restrict__ x,    // [512, 512]
    const float* __restrict__ w2,   // [256, 512]
    const float* __restrict__ b2,   // [256]
    const float* __restrict__ w3,   // [55, 256]
    const float* __restrict__ b3,   // [55]
    float* __restrict__ out)        // [512, 99999]
{
    extern __shared__ float dsm[];
    float* tile = dsm;             // [2][256*36]
    float* xs   = dsm + 18432;     // [4][512]
    float* sv   = dsm + 20480;     // [4][1284]
    float* hs   = dsm + 25616;     // [4][260]
    float* ps   = dsm + 26656;     // [4][64]
    float* zs   = dsm + 26912;     // [4][60]

    const int t   = threadIdx.x;
    const int B   = blockIdx.x;          // 0..127
    const unsigned pad = (unsigned)B & 3u;

    // ---- load 4 x rows (coalesced float4) ----
    if (t < 512) {
        const int m   = t >> 7;
        const int idx = t & 127;
        float4 v = *reinterpret_cast<const float4*>(
            x + (size_t)(B + 128 * m) * 512 + idx * 4);
        *reinterpret_cast<float4*>(&xs[m * 512 + idx * 4]) = v;
    }

    // ---- prefetch w2 chunk 0 (k in [0,32)) ----
    {
        float* dst = tile;  // buffer 0
        #pragma unroll
        for (int i = 0; i < 4; ++i) {
            const int idx = t + i * 640;
            if (idx < 2048) {
                const int h  = idx >> 3;
                const int kq = (idx & 7) * 4;
                cp_async16(&dst[h * 36 + kq], w2 + (size_t)h * 512 + kq);
            }
        }
        asm volatile("cp.async.commit_group;" ::: "memory");
    }

    // ---- GEMM1: 512 threads own (h = t&255, rows rh & rh+2) ----
    float acc0 = 0.f, acc1 = 0.f;
    const int hh = t & 255;
    const int rh = t >> 8;          // 0 or 1 (for t < 512)

    for (int kc = 0; kc < 16; ++kc) {
        if (kc < 15) {
            float* dst = tile + ((kc + 1) & 1) * 9216;
            const int kbase = (kc + 1) * 32;
            #pragma unroll
            for (int i = 0; i < 4; ++i) {
                const int idx = t + i * 640;
                if (idx < 2048) {
                    const int h  = idx >> 3;
                    const int kq = (idx & 7) * 4;
                    cp_async16(&dst[h * 36 + kq],
                               w2 + (size_t)h * 512 + kbase + kq);
                }
            }
            asm volatile("cp.async.commit_group;" ::: "memory");
            asm volatile("cp.async.wait_group 1;" ::: "memory");
        } else {
            asm volatile("cp.async.wait_group 0;" ::: "memory");
        }
        __syncthreads();

        if (t < 512) {
            const float* tb = tile + (kc & 1) * 9216 + hh * 36;
            const float* x0 = &xs[rh * 512 + kc * 32];
            const float* x1 = &xs[(rh + 2) * 512 + kc * 32];
            #pragma unroll
            for (int kq = 0; kq < 32; kq += 4) {
                const float4 w  = *reinterpret_cast<const float4*>(tb + kq);
                const float4 a0 = *reinterpret_cast<const float4*>(x0 + kq);
                const float4 a1 = *reinterpret_cast<const float4*>(x1 + kq);
                acc0 = fmaf(a0.x, w.x, acc0); acc0 = fmaf(a0.y, w.y, acc0);
                acc0 = fmaf(a0.z, w.z, acc0); acc0 = fmaf(a0.w, w.w, acc0);
                acc1 = fmaf(a1.x, w.x, acc1); acc1 = fmaf(a1.y, w.y, acc1);
                acc1 = fmaf(a1.z, w.z, acc1); acc1 = fmaf(a1.w, w.w, acc1);
            }
        }
        __syncthreads();
    }

    if (t < 512) {
        const float bb = __ldg(b2 + hh);
        float s0 = acc0 + bb, s1 = acc1 + bb;
        hs[rh * 260 + hh]       = (s0 >= 0.f) ? s0 : 0.01f * s0;
        hs[(rh + 2) * 260 + hh] = (s1 >= 0.f) ? s1 : 0.01f * s1;
    }
    __syncthreads();

    // ---- GEMM2: 220 threads, one output each (r = t&3, c = t>>2) ----
    if (t < 220) {
        const int r = t & 3;
        const int c = t >> 2;       // 0..54
        const float4* hv = reinterpret_cast<const float4*>(&hs[r * 260]);
        const float4* wv = reinterpret_cast<const float4*>(w3 + (size_t)c * 256);
        float acc = 0.f;
        #pragma unroll 8
        for (int k = 0; k < 64; ++k) {
            const float4 a = hv[k];
            const float4 w = __ldg(&wv[k]);
            acc = fmaf(a.x, w.x, acc); acc = fmaf(a.y, w.y, acc);
            acc = fmaf(a.z, w.z, acc); acc = fmaf(a.w, w.w, acc);
        }
        zs[r * 60 + c] = acc + __ldg(b3 + c);
    }
    __syncthreads();

    // ---- softmaxes: 4 rows x 6 groups ----
    if (t < 24) {
        const int r     = t / 6;
        const int g     = t - 6 * r;
        const int start = (g == 0) ? 0 : 5 + 10 * (g - 1);
        const int len   = (g == 0) ? 5 : 10;
        float mx = -3.0e38f;
        for (int c = 0; c < len; ++c) mx = fmaxf(mx, zs[r * 60 + start + c]);
        float s = 0.f;
        for (int c = 0; c < len; ++c) s += __expf(zs[r * 60 + start + c] - mx);
        const float inv = 1.0f / s;
        for (int c = 0; c < len; ++c)
            ps[r * 64 + start + c] = __expf(zs[r * 60 + start + c] - mx) * inv;
    }
    __syncthreads();

    // ---- expansion: 8 chunks of 1280 runs; R14 4-row structure ----
    const unsigned ut  = (unsigned)t;
    const unsigned ph  = pad + 4u * ut;     // < 2563
    const unsigned rt  = ph / 10u;
    const unsigned rem = ph - 10u * rt;
    const bool cc1 = (rem + 1u < 10u);
    const bool cc2 = (rem + 2u < 10u);
    const bool cc3 = (rem + 3u < 10u);

    float* o[4];
    float4* ov[4];
    #pragma unroll
    for (int m = 0; m < 4; ++m) {
        o[m]  = out + (size_t)(B + 128 * m) * 99999u;
        ov[m] = reinterpret_cast<float4*>(o[m] + pad);   // 16B-aligned
    }

    for (unsigned bx = 0u; bx < 8u; ++bx) {
        const unsigned rbase = bx * 1280u;

        // sv fill: runs [rbase, rbase + 1282), digit indices shared by 4 rows
        #pragma unroll
        for (unsigned kk = 0; kk < 3u; ++kk) {
            const unsigned ri = ut + kk * 640u;
            if (ri < 1282u) {
                const unsigned r = rbase + ri;
                if (r == 0u) {
                    #pragma unroll
                    for (int m = 0; m < 4; ++m) sv[m * 1284 + ri] = ps[m * 64];
                } else if (r < 10u) {
                    const unsigned i1 = 5u + r;
                    #pragma unroll
                    for (int m = 0; m < 4; ++m)
                        sv[m * 1284 + ri] = ps[m * 64 + 1] * ps[m * 64 + i1];
                } else if (r < 100u) {
                    const unsigned q1 = r / 10u;
                    const unsigned i1 = 5u + q1, i2 = 15u + (r - 10u * q1);
                    #pragma unroll
                    for (int m = 0; m < 4; ++m)
                        sv[m * 1284 + ri] = ps[m * 64 + 2] * ps[m * 64 + i1]
                                          * ps[m * 64 + i2];
                } else if (r < 1000u) {
                    const unsigned q1 = r / 10u, q2 = r / 100u;
                    const unsigned i1 = 5u + q2, i2 = 15u + (q1 - 10u * q2),
                                   i3 = 25u + (r - 10u * q1);
                    #pragma unroll
                    for (int m = 0; m < 4; ++m)
                        sv[m * 1284 + ri] = ps[m * 64 + 3] * ps[m * 64 + i1]
                                          * ps[m * 64 + i2] * ps[m * 64 + i3];
                } else if (r < 10000u) {
                    const unsigned q1 = r / 10u, q2 = r / 100u, q3 = r / 1000u;
                    const unsigned i1 = 5u + q3, i2 = 15u + (q2 - 10u * q3),
                                   i3 = 25u + (q1 - 10u * q2),
                                   i4 = 35u + (r - 10u * q1);
                    #pragma unroll
                    for (int m = 0; m < 4; ++m)
                        sv[m * 1284 + ri] = ps[m * 64 + 4] * ps[m * 64 + i1]
                                          * ps[m * 64 + i2] * ps[m * 64 + i3]
                                          * ps[m * 64 + i4];
                } else {
                    #pragma unroll
                    for (int m = 0; m < 4; ++m) sv[m * 1284 + ri] = 0.f;
                }
            }
        }
        __syncthreads();

        if (bx < 7u) {
            #pragma unroll
            for (int k = 0; k < 5; ++k) {
                const unsigned vi = bx * 3200u + ut + (unsigned)k * 640u;
                const unsigned ri = rt + (unsigned)k * 256u;
                #pragma unroll
                for (int m = 0; m < 4; ++m) {
                    const float f0 = sv[m * 1284 + ri];
                    const float f1 = sv[m * 1284 + ri + 1u];
                    float4 w;
                    w.x = f0;
                    w.y = cc1 ? f0 : f1;
                    w.z = cc2 ? f0 : f1;
                    w.w = cc3 ? f0 : f1;
                    __stcs(&ov[m][vi], w);
                }
            }
            if (bx == 0u) {
                if (ut == 0u) {
                    #pragma unroll
                    for (int m = 0; m < 4; ++m)
                        o[m][0] = ps[m * 64 + 1] * ps[m * 64 + 5];
                } else if (ut < pad) {
                    #pragma unroll
                    for (int m = 0; m < 4; ++m) o[m][ut] = ps[m * 64];
                }
            }
        } else {
            // bx == 7: float4 indices [22400, 24999), guarded
            #pragma unroll
            for (int k = 0; k < 5; ++k) {
                const unsigned vi = 22400u + ut + (unsigned)k * 640u;
                if (vi < 24999u) {
                    const unsigned ri = rt + (unsigned)k * 256u;
                    #pragma unroll
                    for (int m = 0; m < 4; ++m) {
                        const float f0 = sv[m * 1284 + ri];
                        const float f1 = sv[m * 1284 + ri + 1u];
                        float4 w;
                        w.x = f0;
                        w.y = cc1 ? f0 : f1;
                        w.z = cc2 ? f0 : f1;
                        w.w = cc3 ? f0 : f1;
                        __stcs(&ov[m][vi], w);
                    }
                }
            }
            // scalar tail: i in [pad + 99996, 99999), run 9999 = rbase + 1039
            if (ut < 3u - pad) {
                #pragma unroll
                for (int m = 0; m < 4; ++m)
                    o[m][pad + 99996u + ut] = sv[m * 1284 + 1039];
            }
        }
        __syncthreads();   // sv reused next chunk
    }
}

// ---------------------------------------------------------------------------
extern "C" void kernel_launch(void* const* d_in, const int* in_sizes, int n_in,
                              void* d_out, int out_size)
{
    (void)in_sizes; (void)n_in; (void)out_size;
    const float* x  = (const float*)d_in[0];   // [512, 512]
    const float* w2 = (const float*)d_in[1];   // [256, 512]
    const float* b2 = (const float*)d_in[2];   // [256]
    const float* w3 = (const float*)d_in[3];   // [55, 256]
    const float* b3 = (const float*)d_in[4];   // [55]
    float* out = (float*)d_out;                // [512, 99999]

    const int dsm_bytes = 27152 * 4;           // 108,608
    cudaFuncSetAttribute(fused_kernel,
                         cudaFuncAttributeMaxDynamicSharedMemorySize, dsm_bytes);

    fused_kernel<<<128, 640, dsm_bytes>>>(x, w2, b2, w3, b3, out);
}